// round 5
// baseline (speedup 1.0000x reference)
#include <cuda_runtime.h>
#include <math.h>

#define DZ 64
#define HY 112
#define WX 112
#define SLICE (HY*WX)        /* 12544 */
#define NN (DZ*SLICE)        /* 802816 */
#define NNU 802816u
#define NN4 (NN/4)           /* 200704 */
#define BM_WORDS (1u<<23)    /* bitmap for key values in [0, 2^28): 32MB */
#define MAXSRC 512           /* valid src labels are <= 334 */

__device__ int                d_parent[NN];
__device__ int                d_labels[NN];
__device__ unsigned char      d_cat[NN];
__device__ int                d_fg[MAXSRC];
__device__ int                d_bg[MAXSRC];
__device__ unsigned long long d_lsum[NN];
__device__ int                d_ccnt[NN];
__device__ unsigned int       d_bitmap[BM_WORDS];
__device__ unsigned long long d_gsum;
__device__ int                d_gregs;

// ---------------------------------------------------------------- clear
__global__ void k_clear() {
    unsigned int idx = blockIdx.x * blockDim.x + threadIdx.x;
    unsigned int stride = gridDim.x * blockDim.x;
    for (unsigned int i = idx; i < BM_WORDS; i += stride) d_bitmap[i] = 0u;
    for (unsigned int i = idx; i < NN; i += stride) { d_ccnt[i] = 0; d_lsum[i] = 0ull; }
    if (idx < MAXSRC) { d_fg[idx] = 0; d_bg[idx] = 0; }
    if (idx == 0) { d_gsum = 0ull; d_gregs = 0; }
}

// ---------------------------------------------------------------- init: category + parent (4/thread)
__global__ void k_init4(const float* __restrict__ pred, const int* __restrict__ tgt) {
    int t = blockIdx.x * blockDim.x + threadIdx.x;
    if (t >= NN4) return;
    int i0 = t << 2;
    float4 a = *(const float4*)(pred + i0);
    float4 b = *(const float4*)(pred + NN + i0);
    int4   g = *(const int4*)(tgt + i0);
    unsigned int c0 = ((b.x > a.x) ? 1u : 0u) | ((g.x == 1) ? 2u : 0u);
    unsigned int c1 = ((b.y > a.y) ? 1u : 0u) | ((g.y == 1) ? 2u : 0u);
    unsigned int c2 = ((b.z > a.z) ? 1u : 0u) | ((g.z == 1) ? 2u : 0u);
    unsigned int c3 = ((b.w > a.w) ? 1u : 0u) | ((g.w == 1) ? 2u : 0u);
    *(unsigned int*)(d_cat + i0) = c0 | (c1 << 8) | (c2 << 16) | (c3 << 24);
    *(int4*)(d_parent + i0) = make_int4(i0, i0 + 1, i0 + 2, i0 + 3);
}

// ---------------------------------------------------------------- union-find
// Path-halving find + atomicMin hooking (ECL-CC style).
__device__ __forceinline__ int uf_find(int x) {
    while (true) {
        int p = d_parent[x];
        if (p == x) return x;
        int gp = d_parent[p];
        if (gp == p) return p;
        d_parent[x] = gp;                // path halving
        x = gp;
    }
}

__device__ __forceinline__ void uf_union(int a, int b) {
    while (true) {
        a = uf_find(a);
        b = uf_find(b);
        if (a == b) return;
        if (a > b) { int t = a; a = b; b = t; }
        int old = atomicMin(&d_parent[b], a);
        if (old == b) return;
        b = old;
    }
}

// Process one neighbor-row column (jb = row base index for these 4 voxels).
// is6mask: bit (dx+1) set if that dx is a 6-connectivity offset for this (dz,dy).
__device__ __forceinline__ void col_union(int i0, unsigned int B0, int jb,
                                          bool okL, bool okR, int is6mask) {
    unsigned int Bc = *(const unsigned int*)(d_cat + jb);
    unsigned int cm1 = okL ? (unsigned int)d_cat[jb - 1] : 0xFFu;
    unsigned int cp4 = okR ? (unsigned int)d_cat[jb + 4] : 0xFFu;
    unsigned int w[6] = { cm1, Bc & 0xFFu, (Bc >> 8) & 0xFFu,
                          (Bc >> 16) & 0xFFu, (Bc >> 24) & 0xFFu, cp4 };
    #pragma unroll
    for (int v = 0; v < 4; v++) {
        unsigned int c = (B0 >> (8 * v)) & 0xFFu;
        #pragma unroll
        for (int dx = -1; dx <= 1; dx++) {
            int wi = v + 1 + dx;
            if (w[wi] != c) continue;
            if (c == 0u && !((is6mask >> (dx + 1)) & 1)) continue;  // TN: 6-conn only
            uf_union(i0 + v, jb + v + dx);
        }
    }
}

// Fused hook+union over the 13 lexicographically-negative offsets, 4 voxels/thread.
__global__ void k_union4() {
    int t = blockIdx.x * blockDim.x + threadIdx.x;
    if (t >= NN4) return;
    int i0 = t << 2;
    int z = i0 / SLICE; int r = i0 - z * SLICE; int y = r / WX; int x0 = r - y * WX;
    unsigned int B0 = *(const unsigned int*)(d_cat + i0);
    bool okL = (x0 > 0);
    bool okR = (x0 + 4 < WX);
    if (z > 0) {
        int zb = i0 - SLICE;
        if (y > 0)        col_union(i0, B0, zb - WX, okL, okR, 0);       // (-1,-1,*)
                          col_union(i0, B0, zb,      okL, okR, 0b010);   // (-1, 0,*) dx=0 is6
        if (y < HY - 1)   col_union(i0, B0, zb + WX, okL, okR, 0);       // (-1,+1,*)
    }
    if (y > 0)            col_union(i0, B0, i0 - WX, okL, okR, 0b010);   // (0,-1,*) dx=0 is6
    // center row, dx = -1 only (is6 -> allowed for all categories)
    {
        unsigned int cm1 = okL ? (unsigned int)d_cat[i0 - 1] : 0xFFu;
        #pragma unroll
        for (int v = 0; v < 4; v++) {
            unsigned int c = (B0 >> (8 * v)) & 0xFFu;
            unsigned int cj = (v == 0) ? cm1 : ((B0 >> (8 * (v - 1))) & 0xFFu);
            if (cj == c) uf_union(i0 + v, i0 + v - 1);
        }
    }
}

__global__ void k_flatten4() {
    int t = blockIdx.x * blockDim.x + threadIdx.x;
    if (t >= NN4) return;
    int i0 = t << 2;
    int4 L;
    L.x = uf_find(i0);
    L.y = uf_find(i0 + 1);
    L.z = uf_find(i0 + 2);
    L.w = uf_find(i0 + 3);
    *(int4*)(d_labels + i0) = L;     // root == component min index
}

// ---------------------------------------------------------------- region graph,
// emulating the reference's int32-wraparound key semantics (JAX x64 disabled):
//   key32 = int32(Li*N + Lj) per directed 26-neighbor pair, Li != Lj;
//   countable iff 0 <= key32 < 2^28; dedup on wrapped key value;
//   src = key32/N (<=334), dst = key32%N, category from voxel dst.
__device__ __forceinline__ void edge_try(unsigned int key) {
    if (key >= (1u << 28)) return;                  // negative or >= SENT32: dropped
    unsigned int word = key >> 5;
    unsigned int bit = 1u << (key & 31u);
    if (d_bitmap[word] & bit) return;               // bits only ever set: safe skip
    unsigned int old = atomicOr(&d_bitmap[word], bit);
    if (old & bit) return;
    int src = (int)(key / NNU);                     // 0..334
    int dst = (int)(key - (unsigned int)src * NNU); // 0..N-1
    int c2 = (int)d_cat[dst];
    if (c2 == 3)      atomicAdd(&d_fg[src], 1);
    else if (c2 == 0) atomicAdd(&d_bg[src], 1);
}

__device__ __forceinline__ void col_edges(const unsigned int* Lv, int jb,
                                          bool okL, bool okR, bool center) {
    int4 B = *(const int4*)(d_labels + jb);
    int wm1 = okL ? d_labels[jb - 1] : 0;
    int wp4 = okR ? d_labels[jb + 4] : 0;
    int w[6] = { wm1, B.x, B.y, B.z, B.w, wp4 };
    #pragma unroll
    for (int v = 0; v < 4; v++) {
        unsigned int L = Lv[v];
        unsigned int base = L * NNU;                // wraps mod 2^32 like the reference
        #pragma unroll
        for (int dx = -1; dx <= 1; dx++) {
            if (center && dx == 0) continue;        // self
            int wi = v + 1 + dx;
            if (wi == 0 && !okL) continue;
            if (wi == 5 && !okR) continue;
            unsigned int Lj = (unsigned int)w[wi];
            if (Lj == L) continue;
            edge_try(base + Lj);
        }
    }
}

__global__ void k_edges4() {
    int t = blockIdx.x * blockDim.x + threadIdx.x;
    if (t >= NN4) return;
    int i0 = t << 2;
    int z = i0 / SLICE; int r = i0 - z * SLICE; int y = r / WX; int x0 = r - y * WX;
    bool okL = (x0 > 0);
    bool okR = (x0 + 4 < WX);
    int4 Li = *(const int4*)(d_labels + i0);
    unsigned int Lv[4] = { (unsigned int)Li.x, (unsigned int)Li.y,
                           (unsigned int)Li.z, (unsigned int)Li.w };
    #pragma unroll
    for (int dz = -1; dz <= 1; dz++) {
        int nz = z + dz;
        if (nz < 0 || nz >= DZ) continue;
        #pragma unroll
        for (int dy = -1; dy <= 1; dy++) {
            int ny = y + dy;
            if (ny < 0 || ny >= HY) continue;
            int jb = i0 + dz * SLICE + dy * WX;
            col_edges(Lv, jb, okL, okR, (dz == 0 && dy == 0));
        }
    }
}

// ---------------------------------------------------------------- per-voxel loss (fixed point)
__global__ void k_loss4(const float* __restrict__ pred) {
    int t = blockIdx.x * blockDim.x + threadIdx.x;
    if (t >= NN4) return;
    int i0 = t << 2;
    unsigned int cc = *(const unsigned int*)(d_cat + i0);
    // fast skip: any byte equal to 1 or 2? (bytes are 0..3)
    int4 Li = *(const int4*)(d_labels + i0);
    int Ls[4] = { Li.x, Li.y, Li.z, Li.w };
    #pragma unroll
    for (int v = 0; v < 4; v++) {
        unsigned int c = (cc >> (8 * v)) & 0xFFu;
        if (c != 1u && c != 2u) continue;           // only FP/FN voxels
        int L = Ls[v];
        if (L < MAXSRC && d_fg[L] == 1 && d_bg[L] == 1) continue;  // non-critical
        int i = i0 + v;
        float p0 = pred[i], p1 = pred[NN + i];
        float p = 1.0f / (1.0f + expf(p0 - p1));    // softmax channel 1
        float g = (c == 2u) ? 1.0f : 0.0f;          // FN => gt foreground
        float d = p - g;
        double vv = (double)d * (double)d;          // in [0,1]
        unsigned long long fx = (unsigned long long)(vv * 4294967296.0);  // Q32.32
        atomicAdd(&d_lsum[L], fx);
        atomicAdd(&d_ccnt[L], 1);
    }
}

// ---------------------------------------------------------------- per-region mean -> global
__global__ void k_regions4() {
    int t = blockIdx.x * blockDim.x + threadIdx.x;
    if (t >= NN4) return;
    int i0 = t << 2;
    int4 c4 = *(const int4*)(d_ccnt + i0);
    if ((c4.x | c4.y | c4.z | c4.w) == 0) return;
    int cs[4] = { c4.x, c4.y, c4.z, c4.w };
    #pragma unroll
    for (int v = 0; v < 4; v++) {
        int cnt = cs[v];
        if (cnt <= 0) continue;
        double mean = (double)d_lsum[i0 + v] * (1.0 / 4294967296.0) / (double)cnt;
        atomicAdd(&d_gsum, (unsigned long long)(mean * 1073741824.0));    // Q34.30
        atomicAdd(&d_gregs, 1);
    }
}

__global__ void k_final(float* __restrict__ out) {
    int r = d_gregs;
    double s = (double)d_gsum * (1.0 / 1073741824.0);
    out[0] = (r > 0) ? (float)(s / (double)r) : 0.0f;
}

// ---------------------------------------------------------------- launch
extern "C" void kernel_launch(void* const* d_in, const int* in_sizes, int n_in,
                              void* d_out, int out_size) {
    const float* pred;
    const int*   tgt;
    if (in_sizes[0] == 2 * NN) {
        pred = (const float*)d_in[0];
        tgt  = (const int*)d_in[1];
    } else {
        pred = (const float*)d_in[1];
        tgt  = (const int*)d_in[0];
    }
    const int T = 256;
    const int G4 = (NN4 + T - 1) / T;   // 784 blocks
    k_clear   <<<4096, T>>>();
    k_init4   <<<G4, T>>>(pred, tgt);
    k_union4  <<<G4, T>>>();
    k_flatten4<<<G4, T>>>();
    k_edges4  <<<G4, T>>>();
    k_loss4   <<<G4, T>>>(pred);
    k_regions4<<<G4, T>>>();
    k_final   <<<1, 1>>>((float*)d_out);
}

// round 6
// speedup vs baseline: 1.0487x; 1.0487x over previous
#include <cuda_runtime.h>
#include <math.h>

#define DZ 64
#define HY 112
#define WX 112
#define SLICE (HY*WX)        /* 12544 */
#define NN (DZ*SLICE)        /* 802816 */
#define NNU 802816u
#define NN4 (NN/4)           /* 200704 */
#define BM_WORDS (1u<<23)    /* bitmap for key values in [0, 2^28): 32MB */
#define MAXSRC 512           /* valid src labels are <= 334 */

__device__ int                d_parent[NN];
__device__ int                d_labels[NN];
__device__ unsigned char      d_cat[NN];
__device__ int                d_fg[MAXSRC];
__device__ int                d_bg[MAXSRC];
__device__ unsigned long long d_lsum[NN];
__device__ int                d_ccnt[NN];
__device__ unsigned int       d_bitmap[BM_WORDS];
__device__ unsigned long long d_gsum;
__device__ int                d_gregs;

// ---------------------------------------------------------------- clear (uint4)
__global__ void k_clear() {
    unsigned int idx = blockIdx.x * blockDim.x + threadIdx.x;
    unsigned int stride = gridDim.x * blockDim.x;
    uint4 z4 = make_uint4(0u, 0u, 0u, 0u);
    uint4* bm = (uint4*)d_bitmap;                   // 2M uint4
    for (unsigned int i = idx; i < (BM_WORDS >> 2); i += stride) bm[i] = z4;
    uint4* ls = (uint4*)d_lsum;                     // NN/2 uint4
    for (unsigned int i = idx; i < (NN >> 1); i += stride) ls[i] = z4;
    uint4* cc = (uint4*)d_ccnt;                     // NN/4 uint4
    for (unsigned int i = idx; i < (NN >> 2); i += stride) cc[i] = z4;
    if (idx < MAXSRC) { d_fg[idx] = 0; d_bg[idx] = 0; }
    if (idx == 0) { d_gsum = 0ull; d_gregs = 0; }
}

// ---------------------------------------------------------------- init: category (4/thread)
__global__ void k_init4(const float* __restrict__ pred, const int* __restrict__ tgt) {
    int t = blockIdx.x * blockDim.x + threadIdx.x;
    if (t >= NN4) return;
    int i0 = t << 2;
    float4 a = *(const float4*)(pred + i0);
    float4 b = *(const float4*)(pred + NN + i0);
    int4   g = *(const int4*)(tgt + i0);
    unsigned int c0 = ((b.x > a.x) ? 1u : 0u) | ((g.x == 1) ? 2u : 0u);
    unsigned int c1 = ((b.y > a.y) ? 1u : 0u) | ((g.y == 1) ? 2u : 0u);
    unsigned int c2 = ((b.z > a.z) ? 1u : 0u) | ((g.z == 1) ? 2u : 0u);
    unsigned int c3 = ((b.w > a.w) ? 1u : 0u) | ((g.w == 1) ? 2u : 0u);
    *(unsigned int*)(d_cat + i0) = c0 | (c1 << 8) | (c2 << 16) | (c3 << 24);
}

// ---------------------------------------------------------------- hook: hint forest (4/thread)
// parent[i] = min same-category neighbor among the 13 negative offsets (else i).
// Every written value is < i -> acyclic forest; component-min stays a root.
__device__ __forceinline__ void col_hook(unsigned int B0, int jb,
                                         bool okL, bool okR, int is6mask, int* best) {
    unsigned int Bc = *(const unsigned int*)(d_cat + jb);
    unsigned int cm1 = okL ? (unsigned int)d_cat[jb - 1] : 0xFFu;
    unsigned int cp4 = okR ? (unsigned int)d_cat[jb + 4] : 0xFFu;
    unsigned int w[6] = { cm1, Bc & 0xFFu, (Bc >> 8) & 0xFFu,
                          (Bc >> 16) & 0xFFu, (Bc >> 24) & 0xFFu, cp4 };
    #pragma unroll
    for (int v = 0; v < 4; v++) {
        unsigned int c = (B0 >> (8 * v)) & 0xFFu;
        #pragma unroll
        for (int dx = -1; dx <= 1; dx++) {
            int wi = v + 1 + dx;
            if (w[wi] != c) continue;
            if (c == 0u && !((is6mask >> (dx + 1)) & 1)) continue;  // TN: 6-conn only
            int j = jb + v + dx;
            if (j < best[v]) best[v] = j;
        }
    }
}

__global__ void k_hook4() {
    int t = blockIdx.x * blockDim.x + threadIdx.x;
    if (t >= NN4) return;
    int i0 = t << 2;
    int z = i0 / SLICE; int r = i0 - z * SLICE; int y = r / WX; int x0 = r - y * WX;
    unsigned int B0 = *(const unsigned int*)(d_cat + i0);
    bool okL = (x0 > 0);
    bool okR = (x0 + 4 < WX);
    int best[4] = { i0, i0 + 1, i0 + 2, i0 + 3 };
    if (z > 0) {
        int zb = i0 - SLICE;
        if (y > 0)        col_hook(B0, zb - WX, okL, okR, 0,     best); // (-1,-1,*)
                          col_hook(B0, zb,      okL, okR, 0b010, best); // (-1, 0,*)
        if (y < HY - 1)   col_hook(B0, zb + WX, okL, okR, 0,     best); // (-1,+1,*)
    }
    if (y > 0)            col_hook(B0, i0 - WX, okL, okR, 0b010, best); // (0,-1,*)
    // center row, dx=-1 (6-conn -> allowed for all categories); since the left
    // in-row neighbor index is smaller than any candidate in earlier rows? no --
    // just take min like the rest.
    {
        unsigned int cm1 = okL ? (unsigned int)d_cat[i0 - 1] : 0xFFu;
        #pragma unroll
        for (int v = 0; v < 4; v++) {
            unsigned int c = (B0 >> (8 * v)) & 0xFFu;
            unsigned int cj = (v == 0) ? cm1 : ((B0 >> (8 * (v - 1))) & 0xFFu);
            int j = i0 + v - 1;
            if (cj == c && j < best[v]) best[v] = j;
        }
    }
    *(int4*)(d_parent + i0) = make_int4(best[0], best[1], best[2], best[3]);
}

// ---------------------------------------------------------------- union-find
// Path-halving find + atomicMin hooking (ECL-CC style).
__device__ __forceinline__ int uf_find(int x) {
    while (true) {
        int p = d_parent[x];
        if (p == x) return x;
        int gp = d_parent[p];
        if (gp == p) return p;
        d_parent[x] = gp;                // path halving
        x = gp;
    }
}

__device__ __forceinline__ void uf_union(int a, int b) {
    while (true) {
        a = uf_find(a);
        b = uf_find(b);
        if (a == b) return;
        if (a > b) { int t = a; a = b; b = t; }
        int old = atomicMin(&d_parent[b], a);
        if (old == b) return;
        b = old;
    }
}

// Process one neighbor-row column (jb = row base index for these 4 voxels).
__device__ __forceinline__ void col_union(int i0, unsigned int B0, int jb,
                                          bool okL, bool okR, int is6mask) {
    unsigned int Bc = *(const unsigned int*)(d_cat + jb);
    unsigned int cm1 = okL ? (unsigned int)d_cat[jb - 1] : 0xFFu;
    unsigned int cp4 = okR ? (unsigned int)d_cat[jb + 4] : 0xFFu;
    unsigned int w[6] = { cm1, Bc & 0xFFu, (Bc >> 8) & 0xFFu,
                          (Bc >> 16) & 0xFFu, (Bc >> 24) & 0xFFu, cp4 };
    #pragma unroll
    for (int v = 0; v < 4; v++) {
        unsigned int c = (B0 >> (8 * v)) & 0xFFu;
        #pragma unroll
        for (int dx = -1; dx <= 1; dx++) {
            int wi = v + 1 + dx;
            if (w[wi] != c) continue;
            if (c == 0u && !((is6mask >> (dx + 1)) & 1)) continue;  // TN: 6-conn only
            uf_union(i0 + v, jb + v + dx);
        }
    }
}

// Union over the 13 lexicographically-negative offsets, 4 voxels/thread.
__global__ void k_union4() {
    int t = blockIdx.x * blockDim.x + threadIdx.x;
    if (t >= NN4) return;
    int i0 = t << 2;
    int z = i0 / SLICE; int r = i0 - z * SLICE; int y = r / WX; int x0 = r - y * WX;
    unsigned int B0 = *(const unsigned int*)(d_cat + i0);
    bool okL = (x0 > 0);
    bool okR = (x0 + 4 < WX);
    if (z > 0) {
        int zb = i0 - SLICE;
        if (y > 0)        col_union(i0, B0, zb - WX, okL, okR, 0);       // (-1,-1,*)
                          col_union(i0, B0, zb,      okL, okR, 0b010);   // (-1, 0,*)
        if (y < HY - 1)   col_union(i0, B0, zb + WX, okL, okR, 0);       // (-1,+1,*)
    }
    if (y > 0)            col_union(i0, B0, i0 - WX, okL, okR, 0b010);   // (0,-1,*)
    {
        unsigned int cm1 = okL ? (unsigned int)d_cat[i0 - 1] : 0xFFu;
        #pragma unroll
        for (int v = 0; v < 4; v++) {
            unsigned int c = (B0 >> (8 * v)) & 0xFFu;
            unsigned int cj = (v == 0) ? cm1 : ((B0 >> (8 * (v - 1))) & 0xFFu);
            if (cj == c) uf_union(i0 + v, i0 + v - 1);
        }
    }
}

__global__ void k_flatten4() {
    int t = blockIdx.x * blockDim.x + threadIdx.x;
    if (t >= NN4) return;
    int i0 = t << 2;
    int4 L;
    L.x = uf_find(i0);
    L.y = uf_find(i0 + 1);
    L.z = uf_find(i0 + 2);
    L.w = uf_find(i0 + 3);
    *(int4*)(d_labels + i0) = L;     // root == component min index
}

// ---------------------------------------------------------------- region graph,
// emulating the reference's int32-wraparound key semantics (JAX x64 disabled):
//   key32 = int32(Li*N + Lj) per directed 26-neighbor pair, Li != Lj;
//   countable iff 0 <= key32 < 2^28; dedup on wrapped key value;
//   src = key32/N (<=334), dst = key32%N, category from voxel dst.
__device__ __forceinline__ void edge_try(unsigned int key) {
    if (key >= (1u << 28)) return;                  // negative or >= SENT32: dropped
    unsigned int word = key >> 5;
    unsigned int bit = 1u << (key & 31u);
    if (d_bitmap[word] & bit) return;               // bits only ever set: safe skip
    unsigned int old = atomicOr(&d_bitmap[word], bit);
    if (old & bit) return;
    int src = (int)(key / NNU);                     // 0..334
    int dst = (int)(key - (unsigned int)src * NNU); // 0..N-1
    int c2 = (int)d_cat[dst];
    if (c2 == 3)      atomicAdd(&d_fg[src], 1);
    else if (c2 == 0) atomicAdd(&d_bg[src], 1);
}

__device__ __forceinline__ void col_edges(const unsigned int* Lv, int jb,
                                          bool okL, bool okR, bool center) {
    int4 B = *(const int4*)(d_labels + jb);
    int wm1 = okL ? d_labels[jb - 1] : 0;
    int wp4 = okR ? d_labels[jb + 4] : 0;
    int w[6] = { wm1, B.x, B.y, B.z, B.w, wp4 };
    #pragma unroll
    for (int v = 0; v < 4; v++) {
        unsigned int L = Lv[v];
        unsigned int base = L * NNU;                // wraps mod 2^32 like the reference
        #pragma unroll
        for (int dx = -1; dx <= 1; dx++) {
            if (center && dx == 0) continue;        // self
            int wi = v + 1 + dx;
            if (wi == 0 && !okL) continue;
            if (wi == 5 && !okR) continue;
            unsigned int Lj = (unsigned int)w[wi];
            if (Lj == L) continue;
            edge_try(base + Lj);
        }
    }
}

__global__ void k_edges4() {
    int t = blockIdx.x * blockDim.x + threadIdx.x;
    if (t >= NN4) return;
    int i0 = t << 2;
    int z = i0 / SLICE; int r = i0 - z * SLICE; int y = r / WX; int x0 = r - y * WX;
    bool okL = (x0 > 0);
    bool okR = (x0 + 4 < WX);
    int4 Li = *(const int4*)(d_labels + i0);
    unsigned int Lv[4] = { (unsigned int)Li.x, (unsigned int)Li.y,
                           (unsigned int)Li.z, (unsigned int)Li.w };
    #pragma unroll
    for (int dz = -1; dz <= 1; dz++) {
        int nz = z + dz;
        if (nz < 0 || nz >= DZ) continue;
        #pragma unroll
        for (int dy = -1; dy <= 1; dy++) {
            int ny = y + dy;
            if (ny < 0 || ny >= HY) continue;
            int jb = i0 + dz * SLICE + dy * WX;
            col_edges(Lv, jb, okL, okR, (dz == 0 && dy == 0));
        }
    }
}

// ---------------------------------------------------------------- per-voxel loss (fixed point)
__global__ void k_loss4(const float* __restrict__ pred) {
    int t = blockIdx.x * blockDim.x + threadIdx.x;
    if (t >= NN4) return;
    int i0 = t << 2;
    unsigned int cc = *(const unsigned int*)(d_cat + i0);
    int4 Li = *(const int4*)(d_labels + i0);
    int Ls[4] = { Li.x, Li.y, Li.z, Li.w };
    #pragma unroll
    for (int v = 0; v < 4; v++) {
        unsigned int c = (cc >> (8 * v)) & 0xFFu;
        if (c != 1u && c != 2u) continue;           // only FP/FN voxels
        int L = Ls[v];
        if (L < MAXSRC && d_fg[L] == 1 && d_bg[L] == 1) continue;  // non-critical
        int i = i0 + v;
        float p0 = pred[i], p1 = pred[NN + i];
        float p = 1.0f / (1.0f + expf(p0 - p1));    // softmax channel 1
        float g = (c == 2u) ? 1.0f : 0.0f;          // FN => gt foreground
        float d = p - g;
        double vv = (double)d * (double)d;          // in [0,1]
        unsigned long long fx = (unsigned long long)(vv * 4294967296.0);  // Q32.32
        atomicAdd(&d_lsum[L], fx);
        atomicAdd(&d_ccnt[L], 1);
    }
}

// ---------------------------------------------------------------- per-region mean -> global
__global__ void k_regions4() {
    int t = blockIdx.x * blockDim.x + threadIdx.x;
    if (t >= NN4) return;
    int i0 = t << 2;
    int4 c4 = *(const int4*)(d_ccnt + i0);
    if ((c4.x | c4.y | c4.z | c4.w) == 0) return;
    int cs[4] = { c4.x, c4.y, c4.z, c4.w };
    #pragma unroll
    for (int v = 0; v < 4; v++) {
        int cnt = cs[v];
        if (cnt <= 0) continue;
        double mean = (double)d_lsum[i0 + v] * (1.0 / 4294967296.0) / (double)cnt;
        atomicAdd(&d_gsum, (unsigned long long)(mean * 1073741824.0));    // Q34.30
        atomicAdd(&d_gregs, 1);
    }
}

__global__ void k_final(float* __restrict__ out) {
    int r = d_gregs;
    double s = (double)d_gsum * (1.0 / 1073741824.0);
    out[0] = (r > 0) ? (float)(s / (double)r) : 0.0f;
}

// ---------------------------------------------------------------- launch
extern "C" void kernel_launch(void* const* d_in, const int* in_sizes, int n_in,
                              void* d_out, int out_size) {
    const float* pred;
    const int*   tgt;
    if (in_sizes[0] == 2 * NN) {
        pred = (const float*)d_in[0];
        tgt  = (const int*)d_in[1];
    } else {
        pred = (const float*)d_in[1];
        tgt  = (const int*)d_in[0];
    }
    const int T = 256;
    const int G4 = (NN4 + T - 1) / T;   // 784 blocks
    k_clear   <<<2048, T>>>();
    k_init4   <<<G4, T>>>(pred, tgt);
    k_hook4   <<<G4, T>>>();
    k_union4  <<<G4, T>>>();
    k_flatten4<<<G4, T>>>();
    k_edges4  <<<G4, T>>>();
    k_loss4   <<<G4, T>>>(pred);
    k_regions4<<<G4, T>>>();
    k_final   <<<1, 1>>>((float*)d_out);
}

// round 9
// speedup vs baseline: 1.7439x; 1.6630x over previous
#include <cuda_runtime.h>
#include <math.h>

#define DZ 64
#define HY 112
#define WX 112
#define SLICE (HY*WX)        /* 12544 */
#define NN (DZ*SLICE)        /* 802816 */
#define NNU 802816u
#define NN4 (NN/4)           /* 200704 */
#define BM_WORDS (1u<<23)    /* bitmap for key values in [0, 2^28): 32MB */
#define MAXSRC 512           /* valid src labels are <= 334 */

__device__ int                d_parent[NN];
__device__ int                d_labels[NN];
__device__ unsigned char      d_cat[NN];
__device__ int                d_fg[MAXSRC];
__device__ int                d_bg[MAXSRC];
__device__ unsigned long long d_lsum[NN];
__device__ int                d_ccnt[NN];
__device__ unsigned int       d_bitmap[BM_WORDS];
__device__ unsigned long long d_gsum;
__device__ int                d_gregs;

// 13 lexicographically-negative offsets {dz,dy,dx,is6}
__device__ __constant__ int c_off[13][4] = {
    {-1,-1,-1,0},{-1,-1, 0,0},{-1,-1, 1,0},
    {-1, 0,-1,0},{-1, 0, 0,1},{-1, 0, 1,0},
    {-1, 1,-1,0},{-1, 1, 0,0},{-1, 1, 1,0},
    { 0,-1,-1,0},{ 0,-1, 0,1},{ 0,-1, 1,0},
    { 0, 0,-1,1}
};

// ---------------------------------------------------------------- clear (uint4)
__global__ void k_clear() {
    unsigned int idx = blockIdx.x * blockDim.x + threadIdx.x;
    unsigned int stride = gridDim.x * blockDim.x;
    uint4 z4 = make_uint4(0u, 0u, 0u, 0u);
    uint4* bm = (uint4*)d_bitmap;                   // 2M uint4
    for (unsigned int i = idx; i < (BM_WORDS >> 2); i += stride) bm[i] = z4;
    uint4* ls = (uint4*)d_lsum;                     // NN/2 uint4
    for (unsigned int i = idx; i < (NN >> 1); i += stride) ls[i] = z4;
    uint4* cc = (uint4*)d_ccnt;                     // NN/4 uint4
    for (unsigned int i = idx; i < (NN >> 2); i += stride) cc[i] = z4;
    if (idx < MAXSRC) { d_fg[idx] = 0; d_bg[idx] = 0; }
    if (idx == 0) { d_gsum = 0ull; d_gregs = 0; }
}

// ---------------------------------------------------------------- init: category (4/thread)
__global__ void k_init4(const float* __restrict__ pred, const int* __restrict__ tgt) {
    int t = blockIdx.x * blockDim.x + threadIdx.x;
    if (t >= NN4) return;
    int i0 = t << 2;
    float4 a = *(const float4*)(pred + i0);
    float4 b = *(const float4*)(pred + NN + i0);
    int4   g = *(const int4*)(tgt + i0);
    unsigned int c0 = ((b.x > a.x) ? 1u : 0u) | ((g.x == 1) ? 2u : 0u);
    unsigned int c1 = ((b.y > a.y) ? 1u : 0u) | ((g.y == 1) ? 2u : 0u);
    unsigned int c2 = ((b.z > a.z) ? 1u : 0u) | ((g.z == 1) ? 2u : 0u);
    unsigned int c3 = ((b.w > a.w) ? 1u : 0u) | ((g.w == 1) ? 2u : 0u);
    *(unsigned int*)(d_cat + i0) = c0 | (c1 << 8) | (c2 << 16) | (c3 << 24);
}

// ---------------------------------------------------------------- hook: hint forest (4/thread)
__device__ __forceinline__ void col_hook(unsigned int B0, int jb,
                                         bool okL, bool okR, int is6mask, int* best) {
    unsigned int Bc = *(const unsigned int*)(d_cat + jb);
    unsigned int cm1 = okL ? (unsigned int)d_cat[jb - 1] : 0xFFu;
    unsigned int cp4 = okR ? (unsigned int)d_cat[jb + 4] : 0xFFu;
    unsigned int w[6] = { cm1, Bc & 0xFFu, (Bc >> 8) & 0xFFu,
                          (Bc >> 16) & 0xFFu, (Bc >> 24) & 0xFFu, cp4 };
    #pragma unroll
    for (int v = 0; v < 4; v++) {
        unsigned int c = (B0 >> (8 * v)) & 0xFFu;
        #pragma unroll
        for (int dx = -1; dx <= 1; dx++) {
            int wi = v + 1 + dx;
            if (w[wi] != c) continue;
            if (c == 0u && !((is6mask >> (dx + 1)) & 1)) continue;  // TN: 6-conn only
            int j = jb + v + dx;
            if (j < best[v]) best[v] = j;
        }
    }
}

__global__ void k_hook4() {
    int t = blockIdx.x * blockDim.x + threadIdx.x;
    if (t >= NN4) return;
    int i0 = t << 2;
    int z = i0 / SLICE; int r = i0 - z * SLICE; int y = r / WX; int x0 = r - y * WX;
    unsigned int B0 = *(const unsigned int*)(d_cat + i0);
    bool okL = (x0 > 0);
    bool okR = (x0 + 4 < WX);
    int best[4] = { i0, i0 + 1, i0 + 2, i0 + 3 };
    if (z > 0) {
        int zb = i0 - SLICE;
        if (y > 0)        col_hook(B0, zb - WX, okL, okR, 0,     best); // (-1,-1,*)
                          col_hook(B0, zb,      okL, okR, 0b010, best); // (-1, 0,*)
        if (y < HY - 1)   col_hook(B0, zb + WX, okL, okR, 0,     best); // (-1,+1,*)
    }
    if (y > 0)            col_hook(B0, i0 - WX, okL, okR, 0b010, best); // (0,-1,*)
    {
        unsigned int cm1 = okL ? (unsigned int)d_cat[i0 - 1] : 0xFFu;
        #pragma unroll
        for (int v = 0; v < 4; v++) {
            unsigned int c = (B0 >> (8 * v)) & 0xFFu;
            unsigned int cj = (v == 0) ? cm1 : ((B0 >> (8 * (v - 1))) & 0xFFu);
            int j = i0 + v - 1;
            if (cj == c && j < best[v]) best[v] = j;
        }
    }
    *(int4*)(d_parent + i0) = make_int4(best[0], best[1], best[2], best[3]);
}

// ---------------------------------------------------------------- union-find
__device__ __forceinline__ int uf_find(int x) {
    while (true) {
        int p = d_parent[x];
        if (p == x) return x;
        int gp = d_parent[p];
        if (gp == p) return p;
        d_parent[x] = gp;                // path halving
        x = gp;
    }
}

__device__ __forceinline__ void uf_union(int a, int b) {
    while (true) {
        a = uf_find(a);
        b = uf_find(b);
        if (a == b) return;
        if (a > b) { int t = a; a = b; b = t; }
        int old = atomicMin(&d_parent[b], a);
        if (old == b) return;
        b = old;
    }
}

// Scalar union: 1 voxel/thread for maximum memory-level parallelism
// (union-find is latency-bound; serializing multiple voxels per thread hurts).
__global__ void k_union() {
    int i = blockIdx.x * blockDim.x + threadIdx.x;
    if (i >= NN) return;
    int c = d_cat[i];
    int z = i / SLICE; int r = i - z * SLICE; int y = r / WX; int x = r - y * WX;
    #pragma unroll
    for (int k = 0; k < 13; k++) {
        if (c == 0 && !c_off[k][3]) continue;      // TN: 6-connectivity only
        int nz = z + c_off[k][0], ny = y + c_off[k][1], nx = x + c_off[k][2];
        if (nz < 0 || ny < 0 || ny >= HY || nx < 0 || nx >= WX) continue;
        int j = i + c_off[k][0] * SLICE + c_off[k][1] * WX + c_off[k][2];
        if ((int)d_cat[j] == c) uf_union(i, j);
    }
}

__global__ void k_flatten4() {
    int t = blockIdx.x * blockDim.x + threadIdx.x;
    if (t >= NN4) return;
    int i0 = t << 2;
    int4 L;
    L.x = uf_find(i0);
    L.y = uf_find(i0 + 1);
    L.z = uf_find(i0 + 2);
    L.w = uf_find(i0 + 3);
    *(int4*)(d_labels + i0) = L;     // root == component min index
}

// ---------------------------------------------------------------- region graph,
// emulating the reference's int32-wraparound key semantics (JAX x64 disabled).
__device__ __forceinline__ void edge_try(unsigned int key) {
    if (key >= (1u << 28)) return;                  // negative or >= SENT32: dropped
    unsigned int word = key >> 5;
    unsigned int bit = 1u << (key & 31u);
    if (d_bitmap[word] & bit) return;               // bits only ever set: safe skip
    unsigned int old = atomicOr(&d_bitmap[word], bit);
    if (old & bit) return;
    int src = (int)(key / NNU);                     // 0..334
    int dst = (int)(key - (unsigned int)src * NNU); // 0..N-1
    int c2 = (int)d_cat[dst];
    if (c2 == 3)      atomicAdd(&d_fg[src], 1);
    else if (c2 == 0) atomicAdd(&d_bg[src], 1);
}

__device__ __forceinline__ void col_edges(const unsigned int* Lv, int jb,
                                          bool okL, bool okR, bool center) {
    int4 B = *(const int4*)(d_labels + jb);
    int wm1 = okL ? d_labels[jb - 1] : 0;
    int wp4 = okR ? d_labels[jb + 4] : 0;
    int w[6] = { wm1, B.x, B.y, B.z, B.w, wp4 };
    #pragma unroll
    for (int v = 0; v < 4; v++) {
        unsigned int L = Lv[v];
        unsigned int base = L * NNU;                // wraps mod 2^32 like the reference
        #pragma unroll
        for (int dx = -1; dx <= 1; dx++) {
            if (center && dx == 0) continue;        // self
            int wi = v + 1 + dx;
            if (wi == 0 && !okL) continue;
            if (wi == 5 && !okR) continue;
            unsigned int Lj = (unsigned int)w[wi];
            if (Lj == L) continue;
            edge_try(base + Lj);
        }
    }
}

__global__ void k_edges4() {
    int t = blockIdx.x * blockDim.x + threadIdx.x;
    if (t >= NN4) return;
    int i0 = t << 2;
    int z = i0 / SLICE; int r = i0 - z * SLICE; int y = r / WX; int x0 = r - y * WX;
    bool okL = (x0 > 0);
    bool okR = (x0 + 4 < WX);
    int4 Li = *(const int4*)(d_labels + i0);
    unsigned int Lv[4] = { (unsigned int)Li.x, (unsigned int)Li.y,
                           (unsigned int)Li.z, (unsigned int)Li.w };
    #pragma unroll
    for (int dz = -1; dz <= 1; dz++) {
        int nz = z + dz;
        if (nz < 0 || nz >= DZ) continue;
        #pragma unroll
        for (int dy = -1; dy <= 1; dy++) {
            int ny = y + dy;
            if (ny < 0 || ny >= HY) continue;
            int jb = i0 + dz * SLICE + dy * WX;
            col_edges(Lv, jb, okL, okR, (dz == 0 && dy == 0));
        }
    }
}

// ---------------------------------------------------------------- per-voxel loss,
// warp-aggregated: one atomic pair per distinct label per warp per sub-voxel.
// Grid is an exact multiple of 256 (NN4 = 784*256) so all warps are full.
// Shuffles use the GROUP mask m (group-uniform trip count) -- legal convergence.
__global__ void k_loss4(const float* __restrict__ pred) {
    int t = blockIdx.x * blockDim.x + threadIdx.x;
    int i0 = t << 2;
    unsigned int cc = *(const unsigned int*)(d_cat + i0);
    int4 Li = *(const int4*)(d_labels + i0);
    int Ls[4] = { Li.x, Li.y, Li.z, Li.w };
    int lane = threadIdx.x & 31;
    #pragma unroll
    for (int v = 0; v < 4; v++) {
        unsigned int c = (cc >> (8 * v)) & 0xFFu;
        int L = Ls[v];
        bool active = (c == 1u || c == 2u);
        if (active && L < MAXSRC && d_fg[L] == 1 && d_bg[L] == 1) active = false;
        unsigned long long fx = 0ull;
        if (active) {
            int i = i0 + v;
            float p0 = pred[i], p1 = pred[NN + i];
            float p = 1.0f / (1.0f + expf(p0 - p1));    // softmax channel 1
            float g = (c == 2u) ? 1.0f : 0.0f;          // FN => gt foreground
            float d = p - g;
            double vv = (double)d * (double)d;          // in [0,1]
            fx = (unsigned long long)(vv * 4294967296.0);  // Q32.32
        }
        int key = active ? L : -1;
        unsigned int m = __match_any_sync(0xFFFFFFFFu, key);
        unsigned long long s = 0ull;
        int cs = 0;
        unsigned int mm = m;
        while (mm) {                                   // same trip count for all of m
            int b = __ffs(mm) - 1;
            s  += __shfl_sync(m, fx, b);               // mask = group -> converged
            cs += (int)__shfl_sync(m, (int)(active ? 1 : 0), b);
            mm &= mm - 1;
        }
        int leader = __ffs(m) - 1;
        if (active && lane == leader) {
            atomicAdd(&d_lsum[L], s);
            atomicAdd(&d_ccnt[L], cs);
        }
    }
}

// ---------------------------------------------------------------- per-region mean -> global
__global__ void k_regions4() {
    int t = blockIdx.x * blockDim.x + threadIdx.x;
    if (t >= NN4) return;
    int i0 = t << 2;
    int4 c4 = *(const int4*)(d_ccnt + i0);
    if ((c4.x | c4.y | c4.z | c4.w) == 0) return;
    int cs[4] = { c4.x, c4.y, c4.z, c4.w };
    #pragma unroll
    for (int v = 0; v < 4; v++) {
        int cnt = cs[v];
        if (cnt <= 0) continue;
        double mean = (double)d_lsum[i0 + v] * (1.0 / 4294967296.0) / (double)cnt;
        atomicAdd(&d_gsum, (unsigned long long)(mean * 1073741824.0));    // Q34.30
        atomicAdd(&d_gregs, 1);
    }
}

__global__ void k_final(float* __restrict__ out) {
    int r = d_gregs;
    double s = (double)d_gsum * (1.0 / 1073741824.0);
    out[0] = (r > 0) ? (float)(s / (double)r) : 0.0f;
}

// ---------------------------------------------------------------- launch
extern "C" void kernel_launch(void* const* d_in, const int* in_sizes, int n_in,
                              void* d_out, int out_size) {
    const float* pred;
    const int*   tgt;
    if (in_sizes[0] == 2 * NN) {
        pred = (const float*)d_in[0];
        tgt  = (const int*)d_in[1];
    } else {
        pred = (const float*)d_in[1];
        tgt  = (const int*)d_in[0];
    }
    const int T = 256;
    const int G4 = (NN4 + T - 1) / T;   // 784 blocks
    const int GB = (NN + T - 1) / T;    // 3136 blocks
    k_clear   <<<2048, T>>>();
    k_init4   <<<G4, T>>>(pred, tgt);
    k_hook4   <<<G4, T>>>();
    k_union   <<<GB, T>>>();            // 4th launch -> profiled slot
    k_flatten4<<<G4, T>>>();
    k_edges4  <<<G4, T>>>();
    k_loss4   <<<G4, T>>>(pred);
    k_regions4<<<G4, T>>>();
    k_final   <<<1, 1>>>((float*)d_out);
}